// round 15
// baseline (speedup 1.0000x reference)
#include <cuda_runtime.h>
#include <cuda_fp16.h>
#include <cstdint>

#define BB   8
#define MM   40000
#define FIN  64
#define KK   6
#define FOUT 64
#define NNZ  320000
#define CW   512    // field width = FIN*BB (halves)
#define CWV  64     // row width in uint4 (8 halves each)
#define NPART ((MM + 255) / 256)   // 157 scan blocks

// Scratch (static device allocs are the sanctioned workaround)
__device__ __align__(16) __half g_Th[KK][MM][CW];   // ~245 MB fp16 fields
__device__ int   g_rowptr[MM + 1];
__device__ int   g_counts[MM];     // invariant: zero at kernel_launch entry
__device__ int   g_off[MM];
__device__ int   g_part[NPART];
__device__ int2  g_edge[NNZ];      // packed {col, val_bits}

// ---------------------------------------------------------------------------
// Fused: blocks [0, HB) do edge histogram; blocks [HB, HB+MM/4) build T0.
// ---------------------------------------------------------------------------
#define HIST_BLOCKS ((NNZ + 255) / 256)
__global__ void __launch_bounds__(256) k_hist_T0(const int* __restrict__ rows,
                                                 const float* __restrict__ x) {
    if (blockIdx.x < HIST_BLOCKS) {
        int e = blockIdx.x * 256 + threadIdx.x;
        if (e < NNZ) atomicAdd(&g_counts[rows[e]], 1);
    } else {
        int bid = blockIdx.x - HIST_BLOCKS;
        int tid = threadIdx.x;
        int m = bid * 4 + (tid >> 6);
        int t = tid & 63;
        int b  = t >> 3;
        int f8 = t & 7;
        const float4* src = reinterpret_cast<const float4*>(
            x + ((size_t)b * MM + m) * 64 + 8 * f8);
        float4 v0 = src[0], v1 = src[1];
        __half2 h0 = __floats2half2_rn(v0.x, v0.y);
        __half2 h1 = __floats2half2_rn(v0.z, v0.w);
        __half2 h2 = __floats2half2_rn(v1.x, v1.y);
        __half2 h3 = __floats2half2_rn(v1.z, v1.w);
        uint4 o;
        o.x = *reinterpret_cast<uint32_t*>(&h0);
        o.y = *reinterpret_cast<uint32_t*>(&h1);
        o.z = *reinterpret_cast<uint32_t*>(&h2);
        o.w = *reinterpret_cast<uint32_t*>(&h3);
        *reinterpret_cast<uint4*>(&g_Th[0][m][8 * t]) = o;
    }
}

// Scan phase 1: per-block sums of counts
__global__ void __launch_bounds__(256) k_scan1() {
    __shared__ int ws[8];
    int i = blockIdx.x * 256 + threadIdx.x;
    int v = (i < MM) ? g_counts[i] : 0;
    int lane = threadIdx.x & 31, wid = threadIdx.x >> 5;
    int s = v;
    #pragma unroll
    for (int o = 1; o < 32; o <<= 1) {
        int u = __shfl_up_sync(0xffffffff, s, o);
        if (lane >= o) s += u;
    }
    if (lane == 31) ws[wid] = s;
    __syncthreads();
    if (threadIdx.x == 0) {
        int tot = 0;
        #pragma unroll
        for (int w = 0; w < 8; w++) tot += ws[w];
        g_part[blockIdx.x] = tot;
    }
}

// Scan phase 2: reduce partials before this block, in-block exclusive scan
// + offset -> rowptr/off. Re-zeroes g_counts (invariant maintenance).
__global__ void __launch_bounds__(256) k_scan3() {
    __shared__ int ws[8];
    __shared__ int s_base;
    int lane = threadIdx.x & 31, wid = threadIdx.x >> 5;

    {
        int t = threadIdx.x;
        int pv = (t < blockIdx.x) ? g_part[t] : 0;
        #pragma unroll
        for (int o = 16; o > 0; o >>= 1)
            pv += __shfl_down_sync(0xffffffff, pv, o);
        if (lane == 0) ws[wid] = pv;
        __syncthreads();
        if (threadIdx.x == 0) {
            int tot = 0;
            #pragma unroll
            for (int w = 0; w < 8; w++) tot += ws[w];
            s_base = tot;
        }
        __syncthreads();
    }

    int i = blockIdx.x * 256 + threadIdx.x;
    int v = (i < MM) ? g_counts[i] : 0;
    int s = v;
    #pragma unroll
    for (int o = 1; o < 32; o <<= 1) {
        int u = __shfl_up_sync(0xffffffff, s, o);
        if (lane >= o) s += u;
    }
    __syncthreads();
    if (lane == 31) ws[wid] = s;
    __syncthreads();
    if (wid == 0) {
        int w = (lane < 8) ? ws[lane] : 0;
        #pragma unroll
        for (int o = 1; o < 8; o <<= 1) {
            int u = __shfl_up_sync(0xffffffff, w, o);
            if (lane >= o) w += u;
        }
        if (lane < 8) ws[lane] = w;
    }
    __syncthreads();
    int warp_off = (wid > 0) ? ws[wid - 1] : 0;
    int excl = s_base + warp_off + (s - v);
    if (i < MM) {
        g_rowptr[i] = excl;
        g_off[i]    = excl;
        g_counts[i] = 0;
    }
    if (blockIdx.x == 0 && threadIdx.x == 0) g_rowptr[MM] = NNZ;
}

__global__ void k_scatter(const int* __restrict__ rows,
                          const int* __restrict__ cols,
                          const float* __restrict__ vals) {
    int e = blockIdx.x * blockDim.x + threadIdx.x;
    if (e < NNZ) {
        int r = rows[e];
        int p = atomicAdd(&g_off[r], 1);
        int2 pk;
        pk.x = cols[e];
        pk.y = __float_as_int(vals[e]);
        g_edge[p] = pk;
    }
}

// ---------------------------------------------------------------------------
// fp16 SpMM + Chebyshev combine (warp-per-row), TAIL-FOLDED:
//   Tnext[r] = alpha * (sum_e val*Tcur[col]  - Tcur[r] - (beta/alpha)*Tprev[r])
// Row self-terms are loaded FIRST and folded into the accumulator init, so
// the post-loop tail is pack+store only (no exposed L2 round-trip).
// ---------------------------------------------------------------------------
__device__ __forceinline__ void acc_uint4(float2* acc, uint4 q, float v) {
    const uint32_t w[4] = {q.x, q.y, q.z, q.w};
    #pragma unroll
    for (int i = 0; i < 4; i++) {
        float2 f = __half22float2(*reinterpret_cast<const __half2*>(&w[i]));
        acc[i].x += v * f.x;
        acc[i].y += v * f.y;
    }
}

__device__ __forceinline__ void init_acc(float2* acc, uint4 qc, uint4 qp,
                                         float ir, bool hb) {
    const uint32_t wc[4] = {qc.x, qc.y, qc.z, qc.w};
    const uint32_t wp[4] = {qp.x, qp.y, qp.z, qp.w};
    #pragma unroll
    for (int i = 0; i < 4; i++) {
        float2 c = __half22float2(*reinterpret_cast<const __half2*>(&wc[i]));
        acc[i].x = -c.x;
        acc[i].y = -c.y;
        if (hb) {
            float2 p = __half22float2(*reinterpret_cast<const __half2*>(&wp[i]));
            acc[i].x -= ir * p.x;
            acc[i].y -= ir * p.y;
        }
    }
}

__device__ __forceinline__ uint4 scale_pack(const float2* acc, float alpha) {
    uint32_t o[4];
    #pragma unroll
    for (int i = 0; i < 4; i++) {
        float2 r;
        r.x = alpha * acc[i].x;
        r.y = alpha * acc[i].y;
        __half2 h = __float22half2_rn(r);
        o[i] = *reinterpret_cast<uint32_t*>(&h);
    }
    uint4 res; res.x = o[0]; res.y = o[1]; res.z = o[2]; res.w = o[3];
    return res;
}

__global__ void __launch_bounds__(256) k_spmm_h(int kidx, float alpha, float beta) {
    int warp = (blockIdx.x * blockDim.x + threadIdx.x) >> 5;
    int lane = threadIdx.x & 31;
    if (warp >= MM) return;
    int r = warp;

    const uint4* Tc = reinterpret_cast<const uint4*>(&g_Th[kidx - 1][0][0]);
    const uint4* Tp = reinterpret_cast<const uint4*>(&g_Th[(kidx >= 2) ? kidx - 2 : 0][0][0]);
    uint4*       Tn = reinterpret_cast<uint4*>(&g_Th[kidx][0][0]);

    bool  hb = (beta != 0.0f);
    float ir = beta / alpha;                 // 0.5 for k>=2 steps

    // Row self-terms first: folded into acc init, consumed immediately.
    const uint4* rowc = Tc + (size_t)r * CWV;
    const uint4* rowp = Tp + (size_t)r * CWV;
    uint4 c0 = __ldg(&rowc[lane]), c1 = __ldg(&rowc[lane + 32]);
    uint4 p0 = c0, p1 = c1;
    if (hb) { p0 = __ldg(&rowp[lane]); p1 = __ldg(&rowp[lane + 32]); }

    float2 acc[8];
    init_acc(acc,     c0, p0, ir, hb);
    init_acc(acc + 4, c1, p1, ir, hb);

    int s = g_rowptr[r], e = g_rowptr[r + 1];
    #pragma unroll 2
    for (int i = s; i < e; i++) {
        int2 pk = __ldg(&g_edge[i]);
        float v = __int_as_float(pk.y);
        const uint4* src = Tc + (size_t)pk.x * CWV;
        uint4 q0 = __ldg(&src[lane]);
        uint4 q1 = __ldg(&src[lane + 32]);
        acc_uint4(acc,     q0, v);
        acc_uint4(acc + 4, q1, v);
    }

    uint4* rown = Tn + (size_t)r * CWV;
    rown[lane]      = scale_pack(acc,     alpha);
    rown[lane + 32] = scale_pack(acc + 4, alpha);
}

// ---------------------------------------------------------------------------
// fp16 tensor-core GEMM, fused + pipelined (proven config):
//   out[b][m][o] = sum_k sum_f Tk[m][b*64+f] * W[f*KK+k][o]
// ---------------------------------------------------------------------------
#define SAH 72
#define A_STAGE (128 * SAH)
#define B_TILE  (64 * SAH)

__device__ __forceinline__ void mma_f16(float* d, const uint32_t* a,
                                        uint32_t b0, uint32_t b1) {
    asm volatile("mma.sync.aligned.m16n8k16.row.col.f32.f16.f16.f32 "
        "{%0,%1,%2,%3}, {%4,%5,%6,%7}, {%8,%9}, {%0,%1,%2,%3};"
        : "+f"(d[0]), "+f"(d[1]), "+f"(d[2]), "+f"(d[3])
        : "r"(a[0]), "r"(a[1]), "r"(a[2]), "r"(a[3]), "r"(b0), "r"(b1));
}

__global__ void __launch_bounds__(256) k_gemm_f16(const float* __restrict__ W,
                                                  float* __restrict__ out) {
    extern __shared__ __half sh[];
    __half* As = sh;                      // 2 * A_STAGE
    __half* Bs = sh + 2 * A_STAGE;        // 6 * B_TILE

    const int b    = blockIdx.y;
    const int m0   = blockIdx.x * 128;
    const int tid  = threadIdx.x;
    const int lane = tid & 31;
    const int warp = tid >> 5;
    const int wm   = warp >> 1;
    const int wn   = warp & 1;
    const int g    = lane >> 2;
    const int tg   = lane & 3;

    auto load_A = [&](int kf, int stage) {
        #pragma unroll
        for (int it = 0; it < 4; it++) {
            int idx = tid + 256 * it;
            int m   = idx >> 3;
            int c   = idx & 7;
            int mg  = m0 + m; if (mg >= MM) mg = MM - 1;
            const void* src = &g_Th[kf][mg][b * 64 + 8 * c];
            uint32_t dst = (uint32_t)__cvta_generic_to_shared(
                &As[stage * A_STAGE + m * SAH + 8 * c]);
            asm volatile("cp.async.ca.shared.global [%0], [%1], 16;\n"
                         :: "r"(dst), "l"(src));
        }
        asm volatile("cp.async.commit_group;\n");
    };

    load_A(0, 0);

    #pragma unroll
    for (int kf = 0; kf < KK; kf++) {
        __half* Bk = Bs + kf * B_TILE;
        #pragma unroll
        for (int it = 0; it < 8; it++) {
            int idx = tid + 256 * it;
            int o   = idx & 63;
            int f   = 2 * (idx >> 6);
            float w0 = __ldg(&W[(size_t)(f * KK + kf) * FOUT + o]);
            float w1 = __ldg(&W[(size_t)((f + 1) * KK + kf) * FOUT + o]);
            __half2 h = __floats2half2_rn(w0, w1);
            *reinterpret_cast<uint32_t*>(&Bk[o * SAH + f]) =
                *reinterpret_cast<uint32_t*>(&h);
        }
    }

    float acc[2][4][4];
    #pragma unroll
    for (int s = 0; s < 2; s++)
        #pragma unroll
        for (int j = 0; j < 4; j++)
            #pragma unroll
            for (int q = 0; q < 4; q++) acc[s][j][q] = 0.f;

    asm volatile("cp.async.wait_group 0;\n");
    __syncthreads();

    for (int kf = 0; kf < KK; kf++) {
        if (kf + 1 < KK) load_A(kf + 1, (kf + 1) & 1);

        const __half* Ak = As + (kf & 1) * A_STAGE;
        const __half* Bk = Bs + kf * B_TILE;

        #pragma unroll
        for (int ks = 0; ks < 4; ks++) {
            int kk = ks * 16;
            uint32_t a[2][4];
            #pragma unroll
            for (int s = 0; s < 2; s++) {
                int mr = wm * 32 + s * 16 + g;
                a[s][0] = *reinterpret_cast<const uint32_t*>(&Ak[(mr)     * SAH + kk + 2 * tg]);
                a[s][1] = *reinterpret_cast<const uint32_t*>(&Ak[(mr + 8) * SAH + kk + 2 * tg]);
                a[s][2] = *reinterpret_cast<const uint32_t*>(&Ak[(mr)     * SAH + kk + 2 * tg + 8]);
                a[s][3] = *reinterpret_cast<const uint32_t*>(&Ak[(mr + 8) * SAH + kk + 2 * tg + 8]);
            }
            #pragma unroll
            for (int j = 0; j < 4; j++) {
                int n = wn * 32 + j * 8 + g;
                uint32_t b0 = *reinterpret_cast<const uint32_t*>(&Bk[n * SAH + kk + 2 * tg]);
                uint32_t b1 = *reinterpret_cast<const uint32_t*>(&Bk[n * SAH + kk + 2 * tg + 8]);
                mma_f16(acc[0][j], a[0], b0, b1);
                mma_f16(acc[1][j], a[1], b0, b1);
            }
        }

        if (kf + 1 < KK) {
            asm volatile("cp.async.wait_group 0;\n");
            __syncthreads();
        }
    }

    #pragma unroll
    for (int s = 0; s < 2; s++) {
        int mrow = m0 + wm * 32 + s * 16 + g;
        #pragma unroll
        for (int j = 0; j < 4; j++) {
            int n = wn * 32 + j * 8 + 2 * tg;
            if (mrow < MM) {
                float2 v = make_float2(acc[s][j][0], acc[s][j][1]);
                *reinterpret_cast<float2*>(out + ((size_t)b * MM + mrow) * FOUT + n) = v;
            }
            if (mrow + 8 < MM) {
                float2 v = make_float2(acc[s][j][2], acc[s][j][3]);
                *reinterpret_cast<float2*>(out + ((size_t)b * MM + mrow + 8) * FOUT + n) = v;
            }
        }
    }
}

// ---------------------------------------------------------------------------
extern "C" void kernel_launch(void* const* d_in, const int* in_sizes, int n_in,
                              void* d_out, int out_size) {
    const float* x  = (const float*)d_in[0];   // [B, M, FIN] f32
    const float* ev = (const float*)d_in[1];   // [NNZ] f32
    const float* W  = (const float*)d_in[2];   // [FIN*K, FOUT] f32
    const int*   er = (const int*)d_in[3];     // [NNZ] int32
    const int*   ec = (const int*)d_in[4];     // [NNZ] int32
    float* out = (float*)d_out;                // [B, M, FOUT] f32

    const int smem_bytes = (2 * A_STAGE + KK * B_TILE) * (int)sizeof(__half);
    static bool attr_set = false;
    if (!attr_set) {
        cudaFuncSetAttribute(k_gemm_f16,
                             cudaFuncAttributeMaxDynamicSharedMemorySize, smem_bytes);
        attr_set = true;
    }

    // CSR build + T0 (g_counts zero on entry; scan3 re-zeroes it)
    k_hist_T0<<<HIST_BLOCKS + MM / 4, 256>>>(er, x);
    k_scan1<<<NPART, 256>>>();
    k_scan3<<<NPART, 256>>>();
    k_scatter<<<(NNZ + 255) / 256, 256>>>(er, ec, ev);

    // Chebyshev chain (warp per row, tail-folded combine)
    int spmm_blocks = (MM * 32 + 255) / 256;
    k_spmm_h<<<spmm_blocks, 256>>>(1, 1.0f, 0.0f);
    for (int k = 2; k < KK; k++)
        k_spmm_h<<<spmm_blocks, 256>>>(k, 2.0f, 1.0f);

    // fp16 tensor-core projection (fused, pipelined)
    dim3 ggrid((MM + 127) / 128, BB);
    k_gemm_f16<<<ggrid, 256, smem_bytes>>>(W, out);
}

// round 16
// speedup vs baseline: 1.0551x; 1.0551x over previous
#include <cuda_runtime.h>
#include <cuda_fp16.h>
#include <cstdint>

#define BB   8
#define MM   40000
#define FIN  64
#define KK   6
#define FOUT 64
#define NNZ  320000
#define CW   512    // field width = FIN*BB (halves)
#define CWV  64     // row width in uint4 (8 halves each)
#define NPART ((MM + 255) / 256)   // 157 scan partials

// Scratch (static device allocs are the sanctioned workaround)
__device__ __align__(16) __half g_Th[KK][MM][CW];   // ~245 MB fp16 fields
__device__ int   g_rowptr[MM + 1];
__device__ int   g_counts[MM];     // invariant: zero at kernel_launch entry
__device__ int   g_off[MM];
__device__ int   g_part[NPART];
__device__ int   g_colS[NNZ];
__device__ float g_valS[NNZ];

// ---------------------------------------------------------------------------
// CSR build
// Fused: blocks [0, HB) do edge histogram; blocks [HB, HB+MM/4) build T0.
// ---------------------------------------------------------------------------
#define HIST_BLOCKS ((NNZ + 255) / 256)
__global__ void __launch_bounds__(256) k_hist_T0(const int* __restrict__ rows,
                                                 const float* __restrict__ x) {
    if (blockIdx.x < HIST_BLOCKS) {
        int e = blockIdx.x * 256 + threadIdx.x;
        if (e < NNZ) atomicAdd(&g_counts[rows[e]], 1);
    } else {
        int bid = blockIdx.x - HIST_BLOCKS;
        int tid = threadIdx.x;
        int m = bid * 4 + (tid >> 6);
        int t = tid & 63;
        int b  = t >> 3;
        int f8 = t & 7;
        const float4* src = reinterpret_cast<const float4*>(
            x + ((size_t)b * MM + m) * 64 + 8 * f8);
        float4 v0 = src[0], v1 = src[1];
        __half2 h0 = __floats2half2_rn(v0.x, v0.y);
        __half2 h1 = __floats2half2_rn(v0.z, v0.w);
        __half2 h2 = __floats2half2_rn(v1.x, v1.y);
        __half2 h3 = __floats2half2_rn(v1.z, v1.w);
        uint4 o;
        o.x = *reinterpret_cast<uint32_t*>(&h0);
        o.y = *reinterpret_cast<uint32_t*>(&h1);
        o.z = *reinterpret_cast<uint32_t*>(&h2);
        o.w = *reinterpret_cast<uint32_t*>(&h3);
        *reinterpret_cast<uint4*>(&g_Th[0][m][8 * t]) = o;
    }
}

// Scan phase 1: per-block sums of counts
__global__ void __launch_bounds__(256) k_scan1() {
    __shared__ int ws[8];
    int i = blockIdx.x * 256 + threadIdx.x;
    int v = (i < MM) ? g_counts[i] : 0;
    int lane = threadIdx.x & 31, wid = threadIdx.x >> 5;
    int s = v;
    #pragma unroll
    for (int o = 1; o < 32; o <<= 1) {
        int u = __shfl_up_sync(0xffffffff, s, o);
        if (lane >= o) s += u;
    }
    if (lane == 31) ws[wid] = s;
    __syncthreads();
    if (threadIdx.x == 0) {
        int tot = 0;
        #pragma unroll
        for (int w = 0; w < 8; w++) tot += ws[w];
        g_part[blockIdx.x] = tot;
    }
}

// Scan phase 2 (final): each block reduces partials before it, then in-block
// exclusive scan + offset -> rowptr / off. Also zeroes g_counts for the next
// replay (invariant maintenance; same work every call).
__global__ void __launch_bounds__(256) k_scan3() {
    __shared__ int ws[8];
    __shared__ int s_base;
    int lane = threadIdx.x & 31, wid = threadIdx.x >> 5;

    // base = sum of g_part[0 .. blockIdx.x-1]
    {
        int t = threadIdx.x;
        int pv = (t < blockIdx.x) ? g_part[t] : 0;   // blockIdx.x <= NPART <= 256
        #pragma unroll
        for (int o = 16; o > 0; o >>= 1)
            pv += __shfl_down_sync(0xffffffff, pv, o);
        if (lane == 0) ws[wid] = pv;
        __syncthreads();
        if (threadIdx.x == 0) {
            int tot = 0;
            #pragma unroll
            for (int w = 0; w < 8; w++) tot += ws[w];
            s_base = tot;
        }
        __syncthreads();
    }

    int i = blockIdx.x * 256 + threadIdx.x;
    int v = (i < MM) ? g_counts[i] : 0;
    int s = v;
    #pragma unroll
    for (int o = 1; o < 32; o <<= 1) {
        int u = __shfl_up_sync(0xffffffff, s, o);
        if (lane >= o) s += u;
    }
    __syncthreads();                    // ws reuse
    if (lane == 31) ws[wid] = s;
    __syncthreads();
    if (wid == 0) {
        int w = (lane < 8) ? ws[lane] : 0;
        #pragma unroll
        for (int o = 1; o < 8; o <<= 1) {
            int u = __shfl_up_sync(0xffffffff, w, o);
            if (lane >= o) w += u;
        }
        if (lane < 8) ws[lane] = w;
    }
    __syncthreads();
    int warp_off = (wid > 0) ? ws[wid - 1] : 0;
    int excl = s_base + warp_off + (s - v);
    if (i < MM) {
        g_rowptr[i] = excl;
        g_off[i]    = excl;
        g_counts[i] = 0;                // reset for next replay
    }
    if (blockIdx.x == 0 && threadIdx.x == 0) g_rowptr[MM] = NNZ;
}

__global__ void k_scatter(const int* __restrict__ rows,
                          const int* __restrict__ cols,
                          const float* __restrict__ vals) {
    int e = blockIdx.x * blockDim.x + threadIdx.x;
    if (e < NNZ) {
        int r = rows[e];
        int p = atomicAdd(&g_off[r], 1);
        g_colS[p] = cols[e];
        g_valS[p] = vals[e];
    }
}

// ---------------------------------------------------------------------------
// fp16 SpMM + Chebyshev combine (warp-per-row, compiler unroll 2):
//   Tnext[r] = alpha * (sum_e val*Tcur[col] - Tcur[r]) - beta * Tprev[r]
// Lane owns uint4 indices {lane, lane+32} of the 64-uint4 row.
// ---------------------------------------------------------------------------
__device__ __forceinline__ void acc_uint4(float2* acc, uint4 q, float v) {
    const uint32_t w[4] = {q.x, q.y, q.z, q.w};
    #pragma unroll
    for (int i = 0; i < 4; i++) {
        float2 f = __half22float2(*reinterpret_cast<const __half2*>(&w[i]));
        acc[i].x += v * f.x;
        acc[i].y += v * f.y;
    }
}

__device__ __forceinline__ uint4 combine_pack(const float2* acc, uint4 qc, uint4 qp,
                                              float alpha, float beta, bool hb) {
    const uint32_t wc[4] = {qc.x, qc.y, qc.z, qc.w};
    const uint32_t wp[4] = {qp.x, qp.y, qp.z, qp.w};
    uint32_t o[4];
    #pragma unroll
    for (int i = 0; i < 4; i++) {
        float2 c = __half22float2(*reinterpret_cast<const __half2*>(&wc[i]));
        float2 r;
        r.x = alpha * (acc[i].x - c.x);
        r.y = alpha * (acc[i].y - c.y);
        if (hb) {
            float2 p = __half22float2(*reinterpret_cast<const __half2*>(&wp[i]));
            r.x -= beta * p.x;
            r.y -= beta * p.y;
        }
        __half2 h = __float22half2_rn(r);
        o[i] = *reinterpret_cast<uint32_t*>(&h);
    }
    uint4 res; res.x = o[0]; res.y = o[1]; res.z = o[2]; res.w = o[3];
    return res;
}

__global__ void __launch_bounds__(256) k_spmm_h(int kidx, float alpha, float beta) {
    int warp = (blockIdx.x * blockDim.x + threadIdx.x) >> 5;
    int lane = threadIdx.x & 31;
    if (warp >= MM) return;
    int r = warp;

    const uint4* Tc = reinterpret_cast<const uint4*>(&g_Th[kidx - 1][0][0]);
    const uint4* Tp = reinterpret_cast<const uint4*>(&g_Th[(kidx >= 2) ? kidx - 2 : 0][0][0]);
    uint4*       Tn = reinterpret_cast<uint4*>(&g_Th[kidx][0][0]);

    float2 acc[8];
    #pragma unroll
    for (int i = 0; i < 8; i++) acc[i] = make_float2(0.f, 0.f);

    int s = g_rowptr[r], e = g_rowptr[r + 1];
    #pragma unroll 2
    for (int i = s; i < e; i++) {
        float v = __ldg(&g_valS[i]);
        int   c = __ldg(&g_colS[i]);
        const uint4* src = Tc + (size_t)c * CWV;
        uint4 q0 = __ldg(&src[lane]);
        uint4 q1 = __ldg(&src[lane + 32]);
        acc_uint4(acc,     q0, v);
        acc_uint4(acc + 4, q1, v);
    }

    bool hb = (beta != 0.0f);
    const uint4* rowc = Tc + (size_t)r * CWV;
    const uint4* rowp = Tp + (size_t)r * CWV;
    uint4*       rown = Tn + (size_t)r * CWV;

    uint4 c0 = rowc[lane], c1 = rowc[lane + 32];
    uint4 p0 = c0, p1 = c1;
    if (hb) { p0 = rowp[lane]; p1 = rowp[lane + 32]; }

    rown[lane]      = combine_pack(acc,     c0, p0, alpha, beta, hb);
    rown[lane + 32] = combine_pack(acc + 4, c1, p1, alpha, beta, hb);
}

// ---------------------------------------------------------------------------
// fp16 tensor-core GEMM, fused + pipelined:
//   out[b][m][o] = sum_k sum_f Tk[m][b*64+f] * W[f*KK+k][o]
// Block 128(M) x 64(N), 8 warps 4x2, warp tile 32x32, mma m16n8k16.
// All 6 B tiles preloaded once; A tile double-buffered via cp.async.
// ---------------------------------------------------------------------------
#define SAH 72
#define A_STAGE (128 * SAH)          // halves per A stage
#define B_TILE  (64 * SAH)           // halves per B tile

__device__ __forceinline__ void mma_f16(float* d, const uint32_t* a,
                                        uint32_t b0, uint32_t b1) {
    asm volatile("mma.sync.aligned.m16n8k16.row.col.f32.f16.f16.f32 "
        "{%0,%1,%2,%3}, {%4,%5,%6,%7}, {%8,%9}, {%0,%1,%2,%3};"
        : "+f"(d[0]), "+f"(d[1]), "+f"(d[2]), "+f"(d[3])
        : "r"(a[0]), "r"(a[1]), "r"(a[2]), "r"(a[3]), "r"(b0), "r"(b1));
}

__global__ void __launch_bounds__(256) k_gemm_f16(const float* __restrict__ W,
                                                  float* __restrict__ out) {
    extern __shared__ __half sh[];
    __half* As = sh;                      // 2 * A_STAGE
    __half* Bs = sh + 2 * A_STAGE;        // 6 * B_TILE, Bs[kf][o][f] transposed

    const int b    = blockIdx.y;
    const int m0   = blockIdx.x * 128;
    const int tid  = threadIdx.x;
    const int lane = tid & 31;
    const int warp = tid >> 5;
    const int wm   = warp >> 1;      // 0..3
    const int wn   = warp & 1;       // 0..1
    const int g    = lane >> 2;      // 0..7
    const int tg   = lane & 3;       // 0..3

    auto load_A = [&](int kf, int stage) {
        #pragma unroll
        for (int it = 0; it < 4; it++) {
            int idx = tid + 256 * it;
            int m   = idx >> 3;          // 0..127
            int c   = idx & 7;           // uint4 within row
            int mg  = m0 + m; if (mg >= MM) mg = MM - 1;
            const void* src = &g_Th[kf][mg][b * 64 + 8 * c];
            uint32_t dst = (uint32_t)__cvta_generic_to_shared(
                &As[stage * A_STAGE + m * SAH + 8 * c]);
            asm volatile("cp.async.ca.shared.global [%0], [%1], 16;\n"
                         :: "r"(dst), "l"(src));
        }
        asm volatile("cp.async.commit_group;\n");
    };

    load_A(0, 0);

    #pragma unroll
    for (int kf = 0; kf < KK; kf++) {
        __half* Bk = Bs + kf * B_TILE;
        #pragma unroll
        for (int it = 0; it < 8; it++) {
            int idx = tid + 256 * it;    // 0..2047
            int o   = idx & 63;
            int f   = 2 * (idx >> 6);    // 0..62 even
            float w0 = __ldg(&W[(size_t)(f * KK + kf) * FOUT + o]);
            float w1 = __ldg(&W[(size_t)((f + 1) * KK + kf) * FOUT + o]);
            __half2 h = __floats2half2_rn(w0, w1);
            *reinterpret_cast<uint32_t*>(&Bk[o * SAH + f]) =
                *reinterpret_cast<uint32_t*>(&h);
        }
    }

    float acc[2][4][4];
    #pragma unroll
    for (int s = 0; s < 2; s++)
        #pragma unroll
        for (int j = 0; j < 4; j++)
            #pragma unroll
            for (int q = 0; q < 4; q++) acc[s][j][q] = 0.f;

    asm volatile("cp.async.wait_group 0;\n");
    __syncthreads();

    for (int kf = 0; kf < KK; kf++) {
        if (kf + 1 < KK) load_A(kf + 1, (kf + 1) & 1);

        const __half* Ak = As + (kf & 1) * A_STAGE;
        const __half* Bk = Bs + kf * B_TILE;

        #pragma unroll
        for (int ks = 0; ks < 4; ks++) {
            int kk = ks * 16;
            uint32_t a[2][4];
            #pragma unroll
            for (int s = 0; s < 2; s++) {
                int mr = wm * 32 + s * 16 + g;
                a[s][0] = *reinterpret_cast<const uint32_t*>(&Ak[(mr)     * SAH + kk + 2 * tg]);
                a[s][1] = *reinterpret_cast<const uint32_t*>(&Ak[(mr + 8) * SAH + kk + 2 * tg]);
                a[s][2] = *reinterpret_cast<const uint32_t*>(&Ak[(mr)     * SAH + kk + 2 * tg + 8]);
                a[s][3] = *reinterpret_cast<const uint32_t*>(&Ak[(mr + 8) * SAH + kk + 2 * tg + 8]);
            }
            #pragma unroll
            for (int j = 0; j < 4; j++) {
                int n = wn * 32 + j * 8 + g;
                uint32_t b0 = *reinterpret_cast<const uint32_t*>(&Bk[n * SAH + kk + 2 * tg]);
                uint32_t b1 = *reinterpret_cast<const uint32_t*>(&Bk[n * SAH + kk + 2 * tg + 8]);
                mma_f16(acc[0][j], a[0], b0, b1);
                mma_f16(acc[1][j], a[1], b0, b1);
            }
        }

        if (kf + 1 < KK) {
            asm volatile("cp.async.wait_group 0;\n");
            __syncthreads();
        }
    }

    // Epilogue: c0=(g,2tg) c1=(g,2tg+1) c2=(g+8,2tg) c3=(g+8,2tg+1)
    #pragma unroll
    for (int s = 0; s < 2; s++) {
        int mrow = m0 + wm * 32 + s * 16 + g;
        #pragma unroll
        for (int j = 0; j < 4; j++) {
            int n = wn * 32 + j * 8 + 2 * tg;
            if (mrow < MM) {
                float2 v = make_float2(acc[s][j][0], acc[s][j][1]);
                *reinterpret_cast<float2*>(out + ((size_t)b * MM + mrow) * FOUT + n) = v;
            }
            if (mrow + 8 < MM) {
                float2 v = make_float2(acc[s][j][2], acc[s][j][3]);
                *reinterpret_cast<float2*>(out + ((size_t)b * MM + mrow + 8) * FOUT + n) = v;
            }
        }
    }
}

// ---------------------------------------------------------------------------
extern "C" void kernel_launch(void* const* d_in, const int* in_sizes, int n_in,
                              void* d_out, int out_size) {
    const float* x  = (const float*)d_in[0];   // [B, M, FIN] f32
    const float* ev = (const float*)d_in[1];   // [NNZ] f32
    const float* W  = (const float*)d_in[2];   // [FIN*K, FOUT] f32
    const int*   er = (const int*)d_in[3];     // [NNZ] int32
    const int*   ec = (const int*)d_in[4];     // [NNZ] int32
    float* out = (float*)d_out;                // [B, M, FOUT] f32

    const int smem_bytes = (2 * A_STAGE + KK * B_TILE) * (int)sizeof(__half);
    static bool attr_set = false;
    if (!attr_set) {
        cudaFuncSetAttribute(k_gemm_f16,
                             cudaFuncAttributeMaxDynamicSharedMemorySize, smem_bytes);
        attr_set = true;
    }

    // CSR build + T0 (g_counts is zero on entry; scan3 re-zeroes it)
    k_hist_T0<<<HIST_BLOCKS + MM / 4, 256>>>(er, x);
    k_scan1<<<NPART, 256>>>();
    k_scan3<<<NPART, 256>>>();
    k_scatter<<<(NNZ + 255) / 256, 256>>>(er, ec, ev);

    // Chebyshev chain (warp per row)
    int spmm_blocks = (MM * 32 + 255) / 256;
    k_spmm_h<<<spmm_blocks, 256>>>(1, 1.0f, 0.0f);
    for (int k = 2; k < KK; k++)
        k_spmm_h<<<spmm_blocks, 256>>>(k, 2.0f, 1.0f);

    // fp16 tensor-core projection (fused, pipelined)
    dim3 ggrid((MM + 127) / 128, BB);
    k_gemm_f16<<<ggrid, 256, smem_bytes>>>(W, out);
}